// round 1
// baseline (speedup 1.0000x reference)
#include <cuda_runtime.h>
#include <math.h>

#define HDIM   256
#define F0DIM  512
#define CDIM   64
#define MAXN   50000

// -------- static device scratch (no allocations allowed) --------
__device__ float g_A[(size_t)MAXN * HDIM];
__device__ float g_B[(size_t)MAXN * HDIM];
__device__ float g_H1[(size_t)MAXN * HDIM];
__device__ float g_H2[(size_t)MAXN * HDIM];
__device__ float g_CAT[(size_t)MAXN * 2 * HDIM];

// ============================================================================
// SGEMM: C[M,N] = A[M,K] @ B[K,N] (+bias[N]) (optional relu). fp32.
// 128x128 tile, BK=16, 256 threads, 8x8 per thread.
// ============================================================================
__global__ void __launch_bounds__(256)
sgemm_kernel(const float* __restrict__ A, const float* __restrict__ B,
             const float* __restrict__ bias, float* __restrict__ C,
             int M, int N, int K, int do_relu)
{
    __shared__ float sA[16][128];
    __shared__ float sB[16][128];

    const int tid = threadIdx.x;
    const int tx  = tid & 15;   // N direction
    const int ty  = tid >> 4;   // M direction
    const int rowBase = blockIdx.y * 128;
    const int colBase = blockIdx.x * 128;

    float acc[8][8];
#pragma unroll
    for (int i = 0; i < 8; i++)
#pragma unroll
        for (int j = 0; j < 8; j++) acc[i][j] = 0.f;

    for (int k0 = 0; k0 < K; k0 += 16) {
        // load A tile (128 rows x 16 cols), transposed into sA[k][m]
#pragma unroll
        for (int i = 0; i < 2; i++) {
            int idx = tid + i * 256;          // 0..511 float4 slots
            int r   = idx >> 2;               // 0..127
            int c4  = (idx & 3) << 2;         // 0,4,8,12
            int grow = rowBase + r;
            float4 v = make_float4(0.f, 0.f, 0.f, 0.f);
            if (grow < M)
                v = *(const float4*)(A + (size_t)grow * K + k0 + c4);
            sA[c4 + 0][r] = v.x;
            sA[c4 + 1][r] = v.y;
            sA[c4 + 2][r] = v.z;
            sA[c4 + 3][r] = v.w;
        }
        // load B tile (16 rows x 128 cols)
#pragma unroll
        for (int i = 0; i < 2; i++) {
            int idx = tid + i * 256;
            int r   = idx >> 5;               // 0..15
            int c4  = (idx & 31) << 2;        // 0..124
            int gcol = colBase + c4;
            float4 v = make_float4(0.f, 0.f, 0.f, 0.f);
            if (gcol < N)
                v = *(const float4*)(B + (size_t)(k0 + r) * N + gcol);
            *(float4*)&sB[r][c4] = v;
        }
        __syncthreads();

#pragma unroll
        for (int kk = 0; kk < 16; kk++) {
            float4 a0 = *(const float4*)&sA[kk][ty * 8];
            float4 a1 = *(const float4*)&sA[kk][ty * 8 + 4];
            float4 b0 = *(const float4*)&sB[kk][tx * 8];
            float4 b1 = *(const float4*)&sB[kk][tx * 8 + 4];
            float a[8] = {a0.x, a0.y, a0.z, a0.w, a1.x, a1.y, a1.z, a1.w};
            float b[8] = {b0.x, b0.y, b0.z, b0.w, b1.x, b1.y, b1.z, b1.w};
#pragma unroll
            for (int i = 0; i < 8; i++)
#pragma unroll
                for (int j = 0; j < 8; j++)
                    acc[i][j] += a[i] * b[j];
        }
        __syncthreads();
    }

    // epilogue: float4 stores, optional bias + relu
#pragma unroll
    for (int i = 0; i < 8; i++) {
        int grow = rowBase + ty * 8 + i;
        if (grow >= M) continue;
#pragma unroll
        for (int jj = 0; jj < 2; jj++) {
            int gcol = colBase + tx * 8 + jj * 4;
            if (gcol >= N) continue;
            float4 v = make_float4(acc[i][jj * 4 + 0], acc[i][jj * 4 + 1],
                                   acc[i][jj * 4 + 2], acc[i][jj * 4 + 3]);
            if (bias) {
                v.x += __ldg(&bias[gcol + 0]);
                v.y += __ldg(&bias[gcol + 1]);
                v.z += __ldg(&bias[gcol + 2]);
                v.w += __ldg(&bias[gcol + 3]);
            }
            if (do_relu) {
                v.x = fmaxf(v.x, 0.f); v.y = fmaxf(v.y, 0.f);
                v.z = fmaxf(v.z, 0.f); v.w = fmaxf(v.w, 0.f);
            }
            *(float4*)(C + (size_t)grow * N + gcol) = v;
        }
    }
}

// ============================================================================
// SpMM: out[dst[e]] += w[e] * h[src[e]]  — one thread per (edge, float4-chunk)
// ============================================================================
__global__ void spmm_kernel(const int* __restrict__ src, const int* __restrict__ dst,
                            const float* __restrict__ w, const float* __restrict__ h,
                            float* __restrict__ out, int E)
{
    long long idx = (long long)blockIdx.x * blockDim.x + threadIdx.x;
    int e = (int)(idx >> 6);          // HDIM/4 = 64 chunks per edge
    if (e >= E) return;
    int c = (int)(idx & 63);
    int s = __ldg(&src[e]);
    int d = __ldg(&dst[e]);
    float wv = __ldg(&w[e]);
    float4 v = __ldg((const float4*)(h + (size_t)s * HDIM) + c);
    float* o = out + (size_t)d * HDIM + (c << 2);
    asm volatile("red.global.add.v4.f32 [%0], {%1, %2, %3, %4};"
                 :: "l"(o), "f"(v.x * wv), "f"(v.y * wv), "f"(v.z * wv), "f"(v.w * wv)
                 : "memory");
}

// ============================================================================
// elementwise bias (+optional relu) over [Nn, HDIM]
// ============================================================================
__global__ void bias_act_kernel(float* __restrict__ buf, const float* __restrict__ bias,
                                int total, int do_relu)
{
    int i = blockIdx.x * blockDim.x + threadIdx.x;
    if (i >= total) return;
    float v = buf[i] + __ldg(&bias[i & (HDIM - 1)]);
    if (do_relu) v = fmaxf(v, 0.f);
    buf[i] = v;
}

// ============================================================================
// row-wise log_softmax, one warp per row, L elems per row (L % 32 == 0)
// ============================================================================
template <int L>
__global__ void logsoftmax_kernel(const float* __restrict__ in, float* __restrict__ out,
                                  int nrows)
{
    int row  = blockIdx.x * (blockDim.x >> 5) + (threadIdx.x >> 5);
    int lane = threadIdx.x & 31;
    if (row >= nrows) return;
    const float* r = in + (size_t)row * L;
    float vals[L / 32];
    float m = -3.4e38f;
#pragma unroll
    for (int t = 0; t < L / 32; t++) {
        vals[t] = r[lane + t * 32];
        m = fmaxf(m, vals[t]);
    }
#pragma unroll
    for (int o = 16; o; o >>= 1) m = fmaxf(m, __shfl_xor_sync(0xffffffffu, m, o));
    float s = 0.f;
#pragma unroll
    for (int t = 0; t < L / 32; t++) s += expf(vals[t] - m);
#pragma unroll
    for (int o = 16; o; o >>= 1) s += __shfl_xor_sync(0xffffffffu, s, o);
    float lse = m + logf(s);
    float* wptr = out + (size_t)row * L;
#pragma unroll
    for (int t = 0; t < L / 32; t++) wptr[lane + t * 32] = vals[t] - lse;
}

// ============================================================================
// host side
// ============================================================================
static void sgemm(const float* A, const float* B, const float* bias, float* C,
                  int M, int N, int K, int relu)
{
    dim3 grid((N + 127) / 128, (M + 127) / 128);
    sgemm_kernel<<<grid, 256>>>(A, B, bias, C, M, N, K, relu);
}

extern "C" void kernel_launch(void* const* d_in, const int* in_sizes, int n_in,
                              void* d_out, int out_size)
{
    const float* x0   = (const float*)d_in[0];
    const float* x1   = (const float*)d_in[1];
    const int*   esrc = (const int*)d_in[2];
    const int*   edst = (const int*)d_in[3];
    const float* ew   = (const float*)d_in[4];
    const float* W1a = (const float*)d_in[5];  const float* b1a = (const float*)d_in[6];
    const float* W2a = (const float*)d_in[7];  const float* b2a = (const float*)d_in[8];
    const float* LWa = (const float*)d_in[9];  const float* Lba = (const float*)d_in[10];
    const float* W1b = (const float*)d_in[11]; const float* b1b = (const float*)d_in[12];
    const float* W2b = (const float*)d_in[13]; const float* b2b = (const float*)d_in[14];
    const float* LWb = (const float*)d_in[15]; const float* Lbb = (const float*)d_in[16];
    const float* LW  = (const float*)d_in[17]; const float* Lb  = (const float*)d_in[18];

    const int Nn = in_sizes[0] / F0DIM;
    const int E  = in_sizes[2];

    float *A, *B, *H1, *H2, *CAT;
    cudaGetSymbolAddress((void**)&A,   g_A);
    cudaGetSymbolAddress((void**)&B,   g_B);
    cudaGetSymbolAddress((void**)&H1,  g_H1);
    cudaGetSymbolAddress((void**)&H2,  g_H2);
    cudaGetSymbolAddress((void**)&CAT, g_CAT);

    const size_t nhBytes = (size_t)Nn * HDIM * sizeof(float);
    const int total  = Nn * HDIM;
    const long long spmmThreads = (long long)E * 64;
    const int spmmBlocks = (int)((spmmThreads + 255) / 256);

    auto branch = [&](const float* x,
                      const float* W1, const float* b1,
                      const float* W2, const float* b2,
                      const float* LWl, const float* Lbl, float* Hout) {
        // t = x @ W1
        sgemm(x, W1, nullptr, A, Nn, HDIM, F0DIM, 0);
        // h = relu(spmm(t) + b1)
        cudaMemsetAsync(B, 0, nhBytes, 0);
        spmm_kernel<<<spmmBlocks, 256>>>(esrc, edst, ew, A, B, E);
        bias_act_kernel<<<(total + 255) / 256, 256>>>(B, b1, total, 1);
        // t = h @ W2
        sgemm(B, W2, nullptr, A, Nn, HDIM, HDIM, 0);
        // h = spmm(t) + b2
        cudaMemsetAsync(B, 0, nhBytes, 0);
        spmm_kernel<<<spmmBlocks, 256>>>(esrc, edst, ew, A, B, E);
        bias_act_kernel<<<(total + 255) / 256, 256>>>(B, b2, total, 0);
        // y = h @ LWl + Lbl ; Hout = log_softmax(y)
        sgemm(B, LWl, Lbl, A, Nn, HDIM, HDIM, 0);
        logsoftmax_kernel<HDIM><<<(Nn + 7) / 8, 256>>>(A, Hout, Nn);
    };

    branch(x0, W1a, b1a, W2a, b2a, LWa, Lba, H1);
    branch(x1, W1b, b1b, W2b, b2b, LWb, Lbb, H2);

    // concat [H1 | H2] -> CAT [Nn, 512]
    cudaMemcpy2DAsync(CAT, 2 * HDIM * sizeof(float),
                      H1, HDIM * sizeof(float),
                      HDIM * sizeof(float), Nn, cudaMemcpyDeviceToDevice, 0);
    cudaMemcpy2DAsync(CAT + HDIM, 2 * HDIM * sizeof(float),
                      H2, HDIM * sizeof(float),
                      HDIM * sizeof(float), Nn, cudaMemcpyDeviceToDevice, 0);

    // final: out = log_softmax(CAT @ LW + Lb)
    sgemm(CAT, LW, Lb, A, Nn, CDIM, 2 * HDIM, 0);
    logsoftmax_kernel<CDIM><<<(Nn + 7) / 8, 256>>>(A, (float*)d_out, Nn);
}

// round 2
// speedup vs baseline: 1.2816x; 1.2816x over previous
#include <cuda_runtime.h>
#include <math.h>

#define HDIM   256
#define F0DIM  512
#define CDIM   64
#define MAXN   50000
#define MAXE   800000

// -------- static device scratch (no allocations allowed) --------
__device__ float g_Aa[(size_t)MAXN * HDIM];
__device__ float g_Ab[(size_t)MAXN * HDIM];
__device__ float g_Ba[(size_t)MAXN * HDIM];
__device__ float g_Bb[(size_t)MAXN * HDIM];
__device__ float g_CAT[(size_t)MAXN * 2 * HDIM];

__device__ int   g_counts[MAXN];
__device__ int   g_cursor[MAXN];
__device__ int   g_rowptr[MAXN + 1];
__device__ int   g_csr_src[MAXE];
__device__ float g_csr_w[MAXE];

// ============================================================================
// SGEMM: C[M,N] = A[M,K] @ B[K,N] (+bias[N]). fp32.
// 128x128 tile, BK=16, 256 threads, 8x8 per thread.
// ============================================================================
__global__ void __launch_bounds__(256)
sgemm_kernel(const float* __restrict__ A, const float* __restrict__ B,
             const float* __restrict__ bias, float* __restrict__ C,
             int M, int N, int K)
{
    __shared__ float sA[16][128];
    __shared__ float sB[16][128];

    const int tid = threadIdx.x;
    const int tx  = tid & 15;   // N direction
    const int ty  = tid >> 4;   // M direction
    const int rowBase = blockIdx.y * 128;
    const int colBase = blockIdx.x * 128;

    float acc[8][8];
#pragma unroll
    for (int i = 0; i < 8; i++)
#pragma unroll
        for (int j = 0; j < 8; j++) acc[i][j] = 0.f;

    for (int k0 = 0; k0 < K; k0 += 16) {
#pragma unroll
        for (int i = 0; i < 2; i++) {
            int idx = tid + i * 256;          // 0..511 float4 slots
            int r   = idx >> 2;               // 0..127
            int c4  = (idx & 3) << 2;         // 0,4,8,12
            int grow = rowBase + r;
            float4 v = make_float4(0.f, 0.f, 0.f, 0.f);
            if (grow < M)
                v = *(const float4*)(A + (size_t)grow * K + k0 + c4);
            sA[c4 + 0][r] = v.x;
            sA[c4 + 1][r] = v.y;
            sA[c4 + 2][r] = v.z;
            sA[c4 + 3][r] = v.w;
        }
#pragma unroll
        for (int i = 0; i < 2; i++) {
            int idx = tid + i * 256;
            int r   = idx >> 5;               // 0..15
            int c4  = (idx & 31) << 2;        // 0..124
            int gcol = colBase + c4;
            float4 v = make_float4(0.f, 0.f, 0.f, 0.f);
            if (gcol < N)
                v = *(const float4*)(B + (size_t)(k0 + r) * N + gcol);
            *(float4*)&sB[r][c4] = v;
        }
        __syncthreads();

#pragma unroll
        for (int kk = 0; kk < 16; kk++) {
            float4 a0 = *(const float4*)&sA[kk][ty * 8];
            float4 a1 = *(const float4*)&sA[kk][ty * 8 + 4];
            float4 b0 = *(const float4*)&sB[kk][tx * 8];
            float4 b1 = *(const float4*)&sB[kk][tx * 8 + 4];
            float a[8] = {a0.x, a0.y, a0.z, a0.w, a1.x, a1.y, a1.z, a1.w};
            float b[8] = {b0.x, b0.y, b0.z, b0.w, b1.x, b1.y, b1.z, b1.w};
#pragma unroll
            for (int i = 0; i < 8; i++)
#pragma unroll
                for (int j = 0; j < 8; j++)
                    acc[i][j] += a[i] * b[j];
        }
        __syncthreads();
    }

#pragma unroll
    for (int i = 0; i < 8; i++) {
        int grow = rowBase + ty * 8 + i;
        if (grow >= M) continue;
#pragma unroll
        for (int jj = 0; jj < 2; jj++) {
            int gcol = colBase + tx * 8 + jj * 4;
            if (gcol >= N) continue;
            float4 v = make_float4(acc[i][jj * 4 + 0], acc[i][jj * 4 + 1],
                                   acc[i][jj * 4 + 2], acc[i][jj * 4 + 3]);
            if (bias) {
                v.x += __ldg(&bias[gcol + 0]);
                v.y += __ldg(&bias[gcol + 1]);
                v.z += __ldg(&bias[gcol + 2]);
                v.w += __ldg(&bias[gcol + 3]);
            }
            *(float4*)(C + (size_t)grow * N + gcol) = v;
        }
    }
}

// ============================================================================
// CSR build: histogram -> scan -> scatter
// ============================================================================
__global__ void count_kernel(const int* __restrict__ dst, int* __restrict__ counts, int E)
{
    int e = blockIdx.x * blockDim.x + threadIdx.x;
    if (e < E) atomicAdd(&counts[dst[e]], 1);
}

__global__ void __launch_bounds__(1024)
scan_kernel(const int* __restrict__ counts, int* __restrict__ rowptr, int n)
{
    __shared__ int sm[1024];
    __shared__ int carry_s;
    int tid = threadIdx.x;
    if (tid == 0) carry_s = 0;
    __syncthreads();
    for (int base = 0; base < n; base += 1024) {
        int v = (base + tid < n) ? counts[base + tid] : 0;
        sm[tid] = v;
        __syncthreads();
#pragma unroll
        for (int off = 1; off < 1024; off <<= 1) {
            int t = (tid >= off) ? sm[tid - off] : 0;
            __syncthreads();
            sm[tid] += t;
            __syncthreads();
        }
        int carry = carry_s;
        if (base + tid < n) rowptr[base + tid] = carry + sm[tid] - v;
        __syncthreads();
        if (tid == 1023) carry_s = carry + sm[1023];
        __syncthreads();
    }
    if (tid == 0) rowptr[n] = carry_s;
}

__global__ void scatter_kernel(const int* __restrict__ src, const int* __restrict__ dst,
                               const float* __restrict__ w,
                               const int* __restrict__ rowptr, int* __restrict__ cursor,
                               int* __restrict__ csr_src, float* __restrict__ csr_w, int E)
{
    int e = blockIdx.x * blockDim.x + threadIdx.x;
    if (e >= E) return;
    int d = dst[e];
    int pos = rowptr[d] + atomicAdd(&cursor[d], 1);
    csr_src[pos] = src[e];
    csr_w[pos]   = w[e];
}

// ============================================================================
// Gather SpMM, both branches fused, bias(+relu) fused.
// 64 threads per node (float4 over 256 features), 4 nodes per 256-thread block.
// ============================================================================
__global__ void __launch_bounds__(256)
spmm_csr_dual_kernel(const int* __restrict__ rowptr,
                     const int* __restrict__ csr_src, const float* __restrict__ csr_w,
                     const float* __restrict__ ha, const float* __restrict__ hb,
                     float* __restrict__ oa, float* __restrict__ ob,
                     const float* __restrict__ bias_a, const float* __restrict__ bias_b,
                     int Nn, int do_relu)
{
    int node = blockIdx.x * 4 + (threadIdx.x >> 6);
    int c    = threadIdx.x & 63;           // float4 chunk 0..63
    if (node >= Nn) return;

    const float4* ha4 = (const float4*)ha;
    const float4* hb4 = (const float4*)hb;

    float4 acca = make_float4(0.f, 0.f, 0.f, 0.f);
    float4 accb = make_float4(0.f, 0.f, 0.f, 0.f);

    int beg = __ldg(&rowptr[node]);
    int end = __ldg(&rowptr[node + 1]);
    for (int i = beg; i < end; i++) {
        int   s = __ldg(&csr_src[i]);
        float w = __ldg(&csr_w[i]);
        float4 va = __ldg(&ha4[(size_t)s * 64 + c]);
        float4 vb = __ldg(&hb4[(size_t)s * 64 + c]);
        acca.x = fmaf(w, va.x, acca.x); acca.y = fmaf(w, va.y, acca.y);
        acca.z = fmaf(w, va.z, acca.z); acca.w = fmaf(w, va.w, acca.w);
        accb.x = fmaf(w, vb.x, accb.x); accb.y = fmaf(w, vb.y, accb.y);
        accb.z = fmaf(w, vb.z, accb.z); accb.w = fmaf(w, vb.w, accb.w);
    }

    float4 ba = __ldg(&((const float4*)bias_a)[c]);
    float4 bb = __ldg(&((const float4*)bias_b)[c]);
    acca.x += ba.x; acca.y += ba.y; acca.z += ba.z; acca.w += ba.w;
    accb.x += bb.x; accb.y += bb.y; accb.z += bb.z; accb.w += bb.w;
    if (do_relu) {
        acca.x = fmaxf(acca.x, 0.f); acca.y = fmaxf(acca.y, 0.f);
        acca.z = fmaxf(acca.z, 0.f); acca.w = fmaxf(acca.w, 0.f);
        accb.x = fmaxf(accb.x, 0.f); accb.y = fmaxf(accb.y, 0.f);
        accb.z = fmaxf(accb.z, 0.f); accb.w = fmaxf(accb.w, 0.f);
    }
    ((float4*)oa)[(size_t)node * 64 + c] = acca;
    ((float4*)ob)[(size_t)node * 64 + c] = accb;
}

// ============================================================================
// row-wise log_softmax, one warp per row; strided output (for concat-free CAT)
// ============================================================================
template <int L>
__global__ void logsoftmax_kernel(const float* __restrict__ in, float* __restrict__ out,
                                  int nrows, int out_stride)
{
    int row  = blockIdx.x * (blockDim.x >> 5) + (threadIdx.x >> 5);
    int lane = threadIdx.x & 31;
    if (row >= nrows) return;
    const float* r = in + (size_t)row * L;
    float vals[L / 32];
    float m = -3.4e38f;
#pragma unroll
    for (int t = 0; t < L / 32; t++) {
        vals[t] = r[lane + t * 32];
        m = fmaxf(m, vals[t]);
    }
#pragma unroll
    for (int o = 16; o; o >>= 1) m = fmaxf(m, __shfl_xor_sync(0xffffffffu, m, o));
    float s = 0.f;
#pragma unroll
    for (int t = 0; t < L / 32; t++) s += expf(vals[t] - m);
#pragma unroll
    for (int o = 16; o; o >>= 1) s += __shfl_xor_sync(0xffffffffu, s, o);
    float lse = m + logf(s);
    float* wptr = out + (size_t)row * out_stride;
#pragma unroll
    for (int t = 0; t < L / 32; t++) wptr[lane + t * 32] = vals[t] - lse;
}

// ============================================================================
// host side
// ============================================================================
static void sgemm(const float* A, const float* B, const float* bias, float* C,
                  int M, int N, int K)
{
    dim3 grid((N + 127) / 128, (M + 127) / 128);
    sgemm_kernel<<<grid, 256>>>(A, B, bias, C, M, N, K);
}

extern "C" void kernel_launch(void* const* d_in, const int* in_sizes, int n_in,
                              void* d_out, int out_size)
{
    const float* x0   = (const float*)d_in[0];
    const float* x1   = (const float*)d_in[1];
    const int*   esrc = (const int*)d_in[2];
    const int*   edst = (const int*)d_in[3];
    const float* ew   = (const float*)d_in[4];
    const float* W1a = (const float*)d_in[5];  const float* b1a = (const float*)d_in[6];
    const float* W2a = (const float*)d_in[7];  const float* b2a = (const float*)d_in[8];
    const float* LWa = (const float*)d_in[9];  const float* Lba = (const float*)d_in[10];
    const float* W1b = (const float*)d_in[11]; const float* b1b = (const float*)d_in[12];
    const float* W2b = (const float*)d_in[13]; const float* b2b = (const float*)d_in[14];
    const float* LWb = (const float*)d_in[15]; const float* Lbb = (const float*)d_in[16];
    const float* LW  = (const float*)d_in[17]; const float* Lb  = (const float*)d_in[18];

    const int Nn = in_sizes[0] / F0DIM;
    const int E  = in_sizes[2];

    float *Aa, *Ab, *Ba, *Bb, *CAT;
    cudaGetSymbolAddress((void**)&Aa,  g_Aa);
    cudaGetSymbolAddress((void**)&Ab,  g_Ab);
    cudaGetSymbolAddress((void**)&Ba,  g_Ba);
    cudaGetSymbolAddress((void**)&Bb,  g_Bb);
    cudaGetSymbolAddress((void**)&CAT, g_CAT);

    int *counts, *cursor, *rowptr, *csr_src;
    float *csr_w;
    cudaGetSymbolAddress((void**)&counts,  g_counts);
    cudaGetSymbolAddress((void**)&cursor,  g_cursor);
    cudaGetSymbolAddress((void**)&rowptr,  g_rowptr);
    cudaGetSymbolAddress((void**)&csr_src, g_csr_src);
    cudaGetSymbolAddress((void**)&csr_w,   g_csr_w);

    // ---- build CSR by dst ----
    cudaMemsetAsync(counts, 0, Nn * sizeof(int), 0);
    cudaMemsetAsync(cursor, 0, Nn * sizeof(int), 0);
    count_kernel<<<(E + 255) / 256, 256>>>(edst, counts, E);
    scan_kernel<<<1, 1024>>>(counts, rowptr, Nn);
    scatter_kernel<<<(E + 255) / 256, 256>>>(esrc, edst, ew, rowptr, cursor,
                                             csr_src, csr_w, E);

    const int spmmGrid = (Nn + 3) / 4;

    // ---- layer 1 ----
    sgemm(x0, W1a, nullptr, Aa, Nn, HDIM, F0DIM);
    sgemm(x1, W1b, nullptr, Ab, Nn, HDIM, F0DIM);
    spmm_csr_dual_kernel<<<spmmGrid, 256>>>(rowptr, csr_src, csr_w,
                                            Aa, Ab, Ba, Bb, b1a, b1b, Nn, 1);
    // ---- layer 2 ----
    sgemm(Ba, W2a, nullptr, Aa, Nn, HDIM, HDIM);
    sgemm(Bb, W2b, nullptr, Ab, Nn, HDIM, HDIM);
    spmm_csr_dual_kernel<<<spmmGrid, 256>>>(rowptr, csr_src, csr_w,
                                            Aa, Ab, Ba, Bb, b2a, b2b, Nn, 0);
    // ---- branch heads: linear + log_softmax directly into CAT (no concat copy) ----
    sgemm(Ba, LWa, Lba, Aa, Nn, HDIM, HDIM);
    sgemm(Bb, LWb, Lbb, Ab, Nn, HDIM, HDIM);
    logsoftmax_kernel<HDIM><<<(Nn + 7) / 8, 256>>>(Aa, CAT,        Nn, 2 * HDIM);
    logsoftmax_kernel<HDIM><<<(Nn + 7) / 8, 256>>>(Ab, CAT + HDIM, Nn, 2 * HDIM);

    // ---- final: out = log_softmax(CAT @ LW + Lb) ----
    sgemm(CAT, LW, Lb, Aa, Nn, CDIM, 2 * HDIM);
    logsoftmax_kernel<CDIM><<<(Nn + 7) / 8, 256>>>(Aa, (float*)d_out, Nn, CDIM);
}

// round 3
// speedup vs baseline: 1.5161x; 1.1830x over previous
#include <cuda_runtime.h>
#include <math.h>
#include <stdint.h>

#define HDIM   256
#define F0DIM  512
#define CDIM   64
#define MAXN   50000
#define MAXE   800000

// -------- static device scratch (no allocations allowed) --------
__device__ float g_Aa[(size_t)MAXN * HDIM];
__device__ float g_Ab[(size_t)MAXN * HDIM];
__device__ float g_Ba[(size_t)MAXN * HDIM];
__device__ float g_Bb[(size_t)MAXN * HDIM];
__device__ float g_CAT[(size_t)MAXN * 2 * HDIM];

__device__ int   g_counts[MAXN];
__device__ int   g_cursor[MAXN];
__device__ int   g_rowptr[MAXN + 1];
__device__ int   g_csr_src[MAXE];
__device__ float g_csr_w[MAXE];

// ============================================================================
// Tensor-core GEMM via mma.sync m16n8k8 tf32, 3xTF32 error compensation.
// C[M,N] = A[M,K] @ B[K,N] (+bias). 128x128 tile, BK=32, 256 thr (8 warps 2x4).
// Warp tile 64x32. Accuracy ~fp32 (lo*hi + hi*lo + hi*hi).
// ============================================================================
#define BM 128
#define BN 128
#define BKK 32
#define SA_STRIDE (BM + 8)
#define SB_STRIDE (BN + 8)

__device__ __forceinline__ uint32_t f2tf32(float x) {
    uint32_t u;
    asm("cvt.rna.tf32.f32 %0, %1;" : "=r"(u) : "f"(x));
    return u;
}

__device__ __forceinline__ void mma_tf32(float c[4], const uint32_t a[4], const uint32_t b[2]) {
    asm volatile(
        "mma.sync.aligned.m16n8k8.row.col.f32.tf32.tf32.f32 "
        "{%0,%1,%2,%3}, {%4,%5,%6,%7}, {%8,%9}, {%0,%1,%2,%3};"
        : "+f"(c[0]), "+f"(c[1]), "+f"(c[2]), "+f"(c[3])
        : "r"(a[0]), "r"(a[1]), "r"(a[2]), "r"(a[3]), "r"(b[0]), "r"(b[1]));
}

__global__ void __launch_bounds__(256)
gemm_tc_kernel(const float* __restrict__ A, const float* __restrict__ B,
               const float* __restrict__ bias, float* __restrict__ C,
               int M, int N, int K)
{
    __shared__ float sA[BKK][SA_STRIDE];   // [k][m]
    __shared__ float sB[BKK][SB_STRIDE];   // [k][n]

    const int tid  = threadIdx.x;
    const int warp = tid >> 5;
    const int lane = tid & 31;
    const int g    = lane >> 2;    // groupID 0..7
    const int tig  = lane & 3;     // thread-in-group 0..3
    const int mBase = (warp & 1) * 64;   // warp M offset within tile
    const int nBase = (warp >> 1) * 32;  // warp N offset within tile
    const int rowBase = blockIdx.y * BM;
    const int colBase = blockIdx.x * BN;

    float acc[4][4][4];
#pragma unroll
    for (int i = 0; i < 4; i++)
#pragma unroll
        for (int j = 0; j < 4; j++)
#pragma unroll
            for (int r = 0; r < 4; r++) acc[i][j][r] = 0.f;

    // global-load indexing
    const int ar   = tid >> 1;                 // A row 0..127
    const int ak0  = (tid & 1) * 16;           // A k offset 0 or 16
    const int br   = tid >> 3;                 // B k-row 0..31
    const int bc0  = (tid & 7) * 16;           // B col offset

    float4 pa[4], pb[4];

    auto loadG = [&](int k0) {
        const int grow = rowBase + ar;
        if (grow < M) {
            const float* ap = A + (size_t)grow * K + k0 + ak0;
#pragma unroll
            for (int j = 0; j < 4; j++) pa[j] = *(const float4*)(ap + j * 4);
        } else {
#pragma unroll
            for (int j = 0; j < 4; j++) pa[j] = make_float4(0.f, 0.f, 0.f, 0.f);
        }
        const float* bp = B + (size_t)(k0 + br) * N + colBase + bc0;
#pragma unroll
        for (int j = 0; j < 4; j++) {
            int gcol = colBase + bc0 + j * 4;
            pb[j] = (gcol < N) ? *(const float4*)(bp + j * 4)
                               : make_float4(0.f, 0.f, 0.f, 0.f);
        }
    };
    auto storeS = [&]() {
#pragma unroll
        for (int j = 0; j < 4; j++) {
            int c = ak0 + j * 4;
            sA[c + 0][ar] = pa[j].x;
            sA[c + 1][ar] = pa[j].y;
            sA[c + 2][ar] = pa[j].z;
            sA[c + 3][ar] = pa[j].w;
            *(float4*)&sB[br][bc0 + j * 4] = pb[j];
        }
    };

    loadG(0);
    storeS();
    __syncthreads();

    for (int k0 = 0; k0 < K; k0 += BKK) {
        const bool has_next = (k0 + BKK) < K;
        if (has_next) loadG(k0 + BKK);

#pragma unroll
        for (int ks = 0; ks < 4; ks++) {
            const int k1 = ks * 8 + tig;
            const int k2 = k1 + 4;

            uint32_t ahi[4][4], alo[4][4];
#pragma unroll
            for (int mi = 0; mi < 4; mi++) {
                const int m0 = mBase + mi * 16 + g;
                float f0 = sA[k1][m0], f1 = sA[k1][m0 + 8];
                float f2 = sA[k2][m0], f3 = sA[k2][m0 + 8];
                ahi[mi][0] = f2tf32(f0); alo[mi][0] = f2tf32(f0 - __uint_as_float(ahi[mi][0]));
                ahi[mi][1] = f2tf32(f1); alo[mi][1] = f2tf32(f1 - __uint_as_float(ahi[mi][1]));
                ahi[mi][2] = f2tf32(f2); alo[mi][2] = f2tf32(f2 - __uint_as_float(ahi[mi][2]));
                ahi[mi][3] = f2tf32(f3); alo[mi][3] = f2tf32(f3 - __uint_as_float(ahi[mi][3]));
            }
            uint32_t bhi[4][2], blo[4][2];
#pragma unroll
            for (int ni = 0; ni < 4; ni++) {
                const int n0 = nBase + ni * 8 + g;
                float f0 = sB[k1][n0], f1 = sB[k2][n0];
                bhi[ni][0] = f2tf32(f0); blo[ni][0] = f2tf32(f0 - __uint_as_float(bhi[ni][0]));
                bhi[ni][1] = f2tf32(f1); blo[ni][1] = f2tf32(f1 - __uint_as_float(bhi[ni][1]));
            }
#pragma unroll
            for (int mi = 0; mi < 4; mi++)
#pragma unroll
                for (int ni = 0; ni < 4; ni++) {
                    mma_tf32(acc[mi][ni], alo[mi], bhi[ni]);
                    mma_tf32(acc[mi][ni], ahi[mi], blo[ni]);
                    mma_tf32(acc[mi][ni], ahi[mi], bhi[ni]);
                }
        }

        __syncthreads();
        if (has_next) {
            storeS();
            __syncthreads();
        }
    }

    // epilogue
#pragma unroll
    for (int mi = 0; mi < 4; mi++) {
#pragma unroll
        for (int ni = 0; ni < 4; ni++) {
            const int col = colBase + nBase + ni * 8 + 2 * tig;
            if (col >= N) continue;
            float bx = 0.f, by = 0.f;
            if (bias) { bx = __ldg(&bias[col]); by = __ldg(&bias[col + 1]); }
            const int row0 = rowBase + mBase + mi * 16 + g;
            const int row1 = row0 + 8;
            if (row0 < M) {
                float2 v = make_float2(acc[mi][ni][0] + bx, acc[mi][ni][1] + by);
                *(float2*)(C + (size_t)row0 * N + col) = v;
            }
            if (row1 < M) {
                float2 v = make_float2(acc[mi][ni][2] + bx, acc[mi][ni][3] + by);
                *(float2*)(C + (size_t)row1 * N + col) = v;
            }
        }
    }
}

// ============================================================================
// CSR build: histogram -> scan -> scatter
// ============================================================================
__global__ void count_kernel(const int* __restrict__ dst, int* __restrict__ counts, int E)
{
    int e = blockIdx.x * blockDim.x + threadIdx.x;
    if (e < E) atomicAdd(&counts[dst[e]], 1);
}

__global__ void __launch_bounds__(1024)
scan_kernel(const int* __restrict__ counts, int* __restrict__ rowptr, int n)
{
    __shared__ int sm[1024];
    __shared__ int carry_s;
    int tid = threadIdx.x;
    if (tid == 0) carry_s = 0;
    __syncthreads();
    for (int base = 0; base < n; base += 1024) {
        int v = (base + tid < n) ? counts[base + tid] : 0;
        sm[tid] = v;
        __syncthreads();
#pragma unroll
        for (int off = 1; off < 1024; off <<= 1) {
            int t = (tid >= off) ? sm[tid - off] : 0;
            __syncthreads();
            sm[tid] += t;
            __syncthreads();
        }
        int carry = carry_s;
        if (base + tid < n) rowptr[base + tid] = carry + sm[tid] - v;
        __syncthreads();
        if (tid == 1023) carry_s = carry + sm[1023];
        __syncthreads();
    }
    if (tid == 0) rowptr[n] = carry_s;
}

__global__ void scatter_kernel(const int* __restrict__ src, const int* __restrict__ dst,
                               const float* __restrict__ w,
                               const int* __restrict__ rowptr, int* __restrict__ cursor,
                               int* __restrict__ csr_src, float* __restrict__ csr_w, int E)
{
    int e = blockIdx.x * blockDim.x + threadIdx.x;
    if (e >= E) return;
    int d = dst[e];
    int pos = rowptr[d] + atomicAdd(&cursor[d], 1);
    csr_src[pos] = src[e];
    csr_w[pos]   = w[e];
}

// ============================================================================
// Gather SpMM, both branches fused, bias(+relu) fused.
// ============================================================================
__global__ void __launch_bounds__(256)
spmm_csr_dual_kernel(const int* __restrict__ rowptr,
                     const int* __restrict__ csr_src, const float* __restrict__ csr_w,
                     const float* __restrict__ ha, const float* __restrict__ hb,
                     float* __restrict__ oa, float* __restrict__ ob,
                     const float* __restrict__ bias_a, const float* __restrict__ bias_b,
                     int Nn, int do_relu)
{
    int node = blockIdx.x * 4 + (threadIdx.x >> 6);
    int c    = threadIdx.x & 63;
    if (node >= Nn) return;

    const float4* ha4 = (const float4*)ha;
    const float4* hb4 = (const float4*)hb;

    float4 acca = make_float4(0.f, 0.f, 0.f, 0.f);
    float4 accb = make_float4(0.f, 0.f, 0.f, 0.f);

    int beg = __ldg(&rowptr[node]);
    int end = __ldg(&rowptr[node + 1]);
    for (int i = beg; i < end; i++) {
        int   s = __ldg(&csr_src[i]);
        float w = __ldg(&csr_w[i]);
        float4 va = __ldg(&ha4[(size_t)s * 64 + c]);
        float4 vb = __ldg(&hb4[(size_t)s * 64 + c]);
        acca.x = fmaf(w, va.x, acca.x); acca.y = fmaf(w, va.y, acca.y);
        acca.z = fmaf(w, va.z, acca.z); acca.w = fmaf(w, va.w, acca.w);
        accb.x = fmaf(w, vb.x, accb.x); accb.y = fmaf(w, vb.y, accb.y);
        accb.z = fmaf(w, vb.z, accb.z); accb.w = fmaf(w, vb.w, accb.w);
    }

    float4 ba = __ldg(&((const float4*)bias_a)[c]);
    float4 bb = __ldg(&((const float4*)bias_b)[c]);
    acca.x += ba.x; acca.y += ba.y; acca.z += ba.z; acca.w += ba.w;
    accb.x += bb.x; accb.y += bb.y; accb.z += bb.z; accb.w += bb.w;
    if (do_relu) {
        acca.x = fmaxf(acca.x, 0.f); acca.y = fmaxf(acca.y, 0.f);
        acca.z = fmaxf(acca.z, 0.f); acca.w = fmaxf(acca.w, 0.f);
        accb.x = fmaxf(accb.x, 0.f); accb.y = fmaxf(accb.y, 0.f);
        accb.z = fmaxf(accb.z, 0.f); accb.w = fmaxf(accb.w, 0.f);
    }
    ((float4*)oa)[(size_t)node * 64 + c] = acca;
    ((float4*)ob)[(size_t)node * 64 + c] = accb;
}

// ============================================================================
// row-wise log_softmax, one warp per row; strided output
// ============================================================================
template <int L>
__global__ void logsoftmax_kernel(const float* __restrict__ in, float* __restrict__ out,
                                  int nrows, int out_stride)
{
    int row  = blockIdx.x * (blockDim.x >> 5) + (threadIdx.x >> 5);
    int lane = threadIdx.x & 31;
    if (row >= nrows) return;
    const float* r = in + (size_t)row * L;
    float vals[L / 32];
    float m = -3.4e38f;
#pragma unroll
    for (int t = 0; t < L / 32; t++) {
        vals[t] = r[lane + t * 32];
        m = fmaxf(m, vals[t]);
    }
#pragma unroll
    for (int o = 16; o; o >>= 1) m = fmaxf(m, __shfl_xor_sync(0xffffffffu, m, o));
    float s = 0.f;
#pragma unroll
    for (int t = 0; t < L / 32; t++) s += expf(vals[t] - m);
#pragma unroll
    for (int o = 16; o; o >>= 1) s += __shfl_xor_sync(0xffffffffu, s, o);
    float lse = m + logf(s);
    float* wptr = out + (size_t)row * out_stride;
#pragma unroll
    for (int t = 0; t < L / 32; t++) wptr[lane + t * 32] = vals[t] - lse;
}

// ============================================================================
// host side
// ============================================================================
static void sgemm(const float* A, const float* B, const float* bias, float* C,
                  int M, int N, int K)
{
    dim3 grid((N + BN - 1) / BN, (M + BM - 1) / BM);
    gemm_tc_kernel<<<grid, 256>>>(A, B, bias, C, M, N, K);
}

extern "C" void kernel_launch(void* const* d_in, const int* in_sizes, int n_in,
                              void* d_out, int out_size)
{
    const float* x0   = (const float*)d_in[0];
    const float* x1   = (const float*)d_in[1];
    const int*   esrc = (const int*)d_in[2];
    const int*   edst = (const int*)d_in[3];
    const float* ew   = (const float*)d_in[4];
    const float* W1a = (const float*)d_in[5];  const float* b1a = (const float*)d_in[6];
    const float* W2a = (const float*)d_in[7];  const float* b2a = (const float*)d_in[8];
    const float* LWa = (const float*)d_in[9];  const float* Lba = (const float*)d_in[10];
    const float* W1b = (const float*)d_in[11]; const float* b1b = (const float*)d_in[12];
    const float* W2b = (const float*)d_in[13]; const float* b2b = (const float*)d_in[14];
    const float* LWb = (const float*)d_in[15]; const float* Lbb = (const float*)d_in[16];
    const float* LW  = (const float*)d_in[17]; const float* Lb  = (const float*)d_in[18];

    const int Nn = in_sizes[0] / F0DIM;
    const int E  = in_sizes[2];

    float *Aa, *Ab, *Ba, *Bb, *CAT;
    cudaGetSymbolAddress((void**)&Aa,  g_Aa);
    cudaGetSymbolAddress((void**)&Ab,  g_Ab);
    cudaGetSymbolAddress((void**)&Ba,  g_Ba);
    cudaGetSymbolAddress((void**)&Bb,  g_Bb);
    cudaGetSymbolAddress((void**)&CAT, g_CAT);

    int *counts, *cursor, *rowptr, *csr_src;
    float *csr_w;
    cudaGetSymbolAddress((void**)&counts,  g_counts);
    cudaGetSymbolAddress((void**)&cursor,  g_cursor);
    cudaGetSymbolAddress((void**)&rowptr,  g_rowptr);
    cudaGetSymbolAddress((void**)&csr_src, g_csr_src);
    cudaGetSymbolAddress((void**)&csr_w,   g_csr_w);

    // ---- build CSR by dst ----
    cudaMemsetAsync(counts, 0, Nn * sizeof(int), 0);
    cudaMemsetAsync(cursor, 0, Nn * sizeof(int), 0);
    count_kernel<<<(E + 255) / 256, 256>>>(edst, counts, E);
    scan_kernel<<<1, 1024>>>(counts, rowptr, Nn);
    scatter_kernel<<<(E + 255) / 256, 256>>>(esrc, edst, ew, rowptr, cursor,
                                             csr_src, csr_w, E);

    const int spmmGrid = (Nn + 3) / 4;

    // ---- layer 1 ----
    sgemm(x0, W1a, nullptr, Aa, Nn, HDIM, F0DIM);
    sgemm(x1, W1b, nullptr, Ab, Nn, HDIM, F0DIM);
    spmm_csr_dual_kernel<<<spmmGrid, 256>>>(rowptr, csr_src, csr_w,
                                            Aa, Ab, Ba, Bb, b1a, b1b, Nn, 1);
    // ---- layer 2 ----
    sgemm(Ba, W2a, nullptr, Aa, Nn, HDIM, HDIM);
    sgemm(Bb, W2b, nullptr, Ab, Nn, HDIM, HDIM);
    spmm_csr_dual_kernel<<<spmmGrid, 256>>>(rowptr, csr_src, csr_w,
                                            Aa, Ab, Ba, Bb, b2a, b2b, Nn, 0);
    // ---- branch heads: linear + log_softmax directly into CAT ----
    sgemm(Ba, LWa, Lba, Aa, Nn, HDIM, HDIM);
    sgemm(Bb, LWb, Lbb, Ab, Nn, HDIM, HDIM);
    logsoftmax_kernel<HDIM><<<(Nn + 7) / 8, 256>>>(Aa, CAT,        Nn, 2 * HDIM);
    logsoftmax_kernel<HDIM><<<(Nn + 7) / 8, 256>>>(Ab, CAT + HDIM, Nn, 2 * HDIM);

    // ---- final: out = log_softmax(CAT @ LW + Lb) ----
    sgemm(CAT, LW, Lb, Aa, Nn, CDIM, 2 * HDIM);
    logsoftmax_kernel<CDIM><<<(Nn + 7) / 8, 256>>>(Aa, (float*)d_out, Nn, CDIM);
}